// round 4
// baseline (speedup 1.0000x reference)
#include <cuda_runtime.h>
#include <cuda.h>
#include <cstdint>
#include <cstddef>

// ============================================================================
// out[M,N] = ((x + 66)*0.03) @ ((y - 160)*0.025),  x s8-range, y u8-range
// Integer reformulation:  a = x (s8),  b = y - 128 (s8)
//   (x+66)(y-160) = (a+66)(b-32) = ab - 32 a + 66 b - 2112
//   out = 7.5e-4 * ( A@B - 32*rowsumA[m] + 66*colsumB[n] - 2112*K )
// Engine: mma.sync.aligned.m16n8k32.s8 (legal on plain sm_103 target; the
// harness does NOT compile for sm_103a, so tcgen05 is unavailable).
// ============================================================================

static constexpr int MDIM = 4096, NDIM = 4096, KDIM = 4096;

static constexpr int TM = 128;        // CTA M tile
static constexpr int TN = 128;        // CTA N tile
static constexpr int TKB = 128;       // K bytes (= k elems, s8) per stage
static constexpr int NK = KDIM / TKB; // 32 mainloop iters
static constexpr int STAGES = 4;
static constexpr int A_STG = TM * TKB;              // 16 KB
static constexpr int B_STG = TN * TKB;              // 16 KB
static constexpr int STAGE_BYTES = A_STG + B_STG;   // 32 KB
static constexpr int SMEM_TOTAL = STAGES * STAGE_BYTES;  // 128 KB

static constexpr int GRID_M = MDIM / TM;  // 32
static constexpr int GRID_N = NDIM / TN;  // 32

static constexpr float OUT_SCALE = 0.03f * 0.025f;        // 7.5e-4
static constexpr int CONST_TERM = -2112 * KDIM;           // -8650752

// Scratch (device globals: no runtime allocation allowed). int4 for alignment.
__device__ int4 g_xa4[(size_t)MDIM * KDIM / 16];   // A  s8 [M,K] (x)
__device__ int4 g_yb4[(size_t)NDIM * KDIM / 16];   // Bt s8 [N,K] (y-128, transposed)
__device__ int  g_rowsumA[MDIM];
__device__ int  g_colsumB[NDIM];

#define DEVINL __device__ __forceinline__

DEVINL uint32_t smem_u32(const void* p) {
    uint32_t a;
    asm("{ .reg .u64 t; cvta.to.shared.u64 t, %1; cvt.u32.u64 %0, t; }"
        : "=r"(a) : "l"(p));
    return a;
}

DEVINL void cp_async16(uint32_t dst, const void* src) {
    asm volatile("cp.async.cg.shared.global [%0], [%1], 16;"
                 :: "r"(dst), "l"(src) : "memory");
}
DEVINL void cp_commit() { asm volatile("cp.async.commit_group;" ::: "memory"); }
template <int N>
DEVINL void cp_wait() { asm volatile("cp.async.wait_group %0;" :: "n"(N) : "memory"); }

DEVINL void ldsm4(uint32_t* r, uint32_t addr) {
    asm volatile("ldmatrix.sync.aligned.m8n8.x4.shared.b16 {%0,%1,%2,%3}, [%4];"
                 : "=r"(r[0]), "=r"(r[1]), "=r"(r[2]), "=r"(r[3]) : "r"(addr));
}

DEVINL void mma_s8(int* c, const uint32_t* a, const uint32_t* b) {
    asm volatile(
        "mma.sync.aligned.m16n8k32.row.col.s32.s8.s8.s32 "
        "{%0,%1,%2,%3}, {%4,%5,%6,%7}, {%8,%9}, {%0,%1,%2,%3};"
        : "+r"(c[0]), "+r"(c[1]), "+r"(c[2]), "+r"(c[3])
        : "r"(a[0]), "r"(a[1]), "r"(a[2]), "r"(a[3]), "r"(b[0]), "r"(b[1]));
}

// ============================================================================
// Conversion kernels
// ============================================================================

// x int32 [M,K] -> s8 [M,K]. Thread: 16 ints -> 16 bytes.
__global__ void convert_x_kernel(const int4* __restrict__ in,
                                 int4* __restrict__ out, int n16) {
    int i = blockIdx.x * blockDim.x + threadIdx.x;
    if (i >= n16) return;
    uint32_t w[4];
#pragma unroll
    for (int j = 0; j < 4; ++j) {
        int4 v = in[i * 4 + j];
        w[j] = (uint32_t)(v.x & 255) | ((uint32_t)(v.y & 255) << 8) |
               ((uint32_t)(v.z & 255) << 16) | ((uint32_t)v.w << 24);
    }
    out[i] = make_int4((int)w[0], (int)w[1], (int)w[2], (int)w[3]);
}

// y int32 [K,N] -> s8 Bt [N,K] with (y - 128). 64x64 tiles via smem.
__global__ void convert_yT_kernel(const int* __restrict__ y,
                                  char* __restrict__ bt) {
    __shared__ char tile[64][80];    // [n][k], padded row 80B (16B-aligned)
    int k0 = blockIdx.y * 64;
    int n0 = blockIdx.x * 64;
    int tid = threadIdx.x;           // 256 threads

#pragma unroll
    for (int q = 0; q < 16; ++q) {
        int idx = q * 256 + tid;
        int kk = idx >> 6;
        int nn = idx & 63;
        int v = y[(size_t)(k0 + kk) * NDIM + n0 + nn] - 128;
        tile[nn][kk] = (char)v;
    }
    __syncthreads();
    {
        int row = tid >> 2;          // n 0..63
        int c = tid & 3;             // 16B chunk 0..3
        uint4 v = *(const uint4*)&tile[row][c * 16];
        *(uint4*)&bt[(size_t)(n0 + row) * KDIM + k0 + c * 16] = v;
    }
}

// Per-row signed-byte sum of an [4096 x 4096] s8 matrix. Block = one row.
__global__ void rowsum_kernel(const int* __restrict__ m, int* __restrict__ sums) {
    __shared__ int red[256];
    const int* row = m + (size_t)blockIdx.x * (KDIM / 4);
    int acc = 0;
#pragma unroll 4
    for (int i = threadIdx.x; i < KDIM / 4; i += 256)
        acc = __dp4a(row[i], 0x01010101, acc);
    red[threadIdx.x] = acc;
    __syncthreads();
    for (int s = 128; s > 0; s >>= 1) {
        if (threadIdx.x < s) red[threadIdx.x] += red[threadIdx.x + s];
        __syncthreads();
    }
    if (threadIdx.x == 0) sums[blockIdx.x] = red[0];
}

// ============================================================================
// GEMM: 128x128 CTA tile, 8 warps (4m x 2n), warp tile 32x64,
// mma.m16n8k32.s8, 4-stage cp.async pipeline, XOR-swizzled smem.
// ============================================================================
__global__ void __launch_bounds__(256, 1)
gemm_kernel(float* __restrict__ out) {
    extern __shared__ __align__(1024) char smem[];
    const uint32_t sb = smem_u32(smem);
    const char* A = (const char*)g_xa4;
    const char* B = (const char*)g_yb4;

    const int tid = threadIdx.x;
    const int lane = tid & 31;
    const int wid = tid >> 5;
    const int wm = wid & 3;       // 0..3
    const int wn = wid >> 2;      // 0..1

    // Rasterization: groups of 8 m-tiles, n fast within group.
    int pid = blockIdx.x;
    int g = pid >> 8;                  // / (8*GRID_N)
    int r = pid & 255;
    int m0 = (g * 8 + (r & 7)) * TM;
    int n0 = (r >> 3) * TN;

    // ldmatrix lane geometry (see fragment layouts of m16n8k32.s8)
    const int a_row16 = ((lane >> 3) & 1) * 8 + (lane & 7);  // row within m16
    const int a_kh = lane >> 4;                              // 16B half of k32
    const int b_row16 = ((lane >> 4) & 1) * 8 + (lane & 7);  // row within n16
    const int b_kh = (lane >> 3) & 1;

    const int rowA0 = wm * 32 + a_row16;        // tm=0 ; tm=1 adds 16
    const int rowB0 = wn * 64 + b_row16;        // gg adds 16

    int acc[64];
#pragma unroll
    for (int i = 0; i < 64; ++i) acc[i] = 0;

    // ---- cp.async stage copy ----
    auto stage_copy = [&](int slot, int kt) {
        uint32_t abase = sb + slot * STAGE_BYTES;
        uint32_t bbase = abase + A_STG;
#pragma unroll
        for (int i = 0; i < 4; ++i) {
            int idx = tid + i * 256;
            int row = idx >> 3, c = idx & 7;
            cp_async16(abase + row * 128 + ((c ^ (row & 7)) << 4),
                       A + (size_t)(m0 + row) * KDIM + kt * TKB + c * 16);
        }
#pragma unroll
        for (int i = 0; i < 4; ++i) {
            int idx = tid + i * 256;
            int row = idx >> 3, c = idx & 7;
            cp_async16(bbase + row * 128 + ((c ^ (row & 7)) << 4),
                       B + (size_t)(n0 + row) * KDIM + kt * TKB + c * 16);
        }
    };

    // ---- prologue: stages 0..2 ----
#pragma unroll
    for (int s = 0; s < STAGES - 1; ++s) {
        stage_copy(s, s);
        cp_commit();
    }

    // ---- mainloop ----
    for (int kt = 0; kt < NK; ++kt) {
        int pf = kt + STAGES - 1;
        if (pf < NK) stage_copy(pf & 3, pf);
        cp_commit();
        cp_wait<STAGES - 1>();
        __syncthreads();

        uint32_t abase = sb + (kt & 3) * STAGE_BYTES;
        uint32_t bbase = abase + A_STG;

#pragma unroll
        for (int ks = 0; ks < 4; ++ks) {
            uint32_t afr[2][4];
#pragma unroll
            for (int tm = 0; tm < 2; ++tm) {
                int rowa = rowA0 + tm * 16;
                ldsm4(afr[tm],
                      abase + rowa * 128 + (((ks * 2 + a_kh) ^ (rowa & 7)) << 4));
            }
            uint32_t bfr[8][2];
#pragma unroll
            for (int gg = 0; gg < 4; ++gg) {
                uint32_t t4[4];
                int rowb = rowB0 + gg * 16;
                ldsm4(t4,
                      bbase + rowb * 128 + (((ks * 2 + b_kh) ^ (rowb & 7)) << 4));
                bfr[2 * gg][0] = t4[0]; bfr[2 * gg][1] = t4[1];
                bfr[2 * gg + 1][0] = t4[2]; bfr[2 * gg + 1][1] = t4[3];
            }
#pragma unroll
            for (int tm = 0; tm < 2; ++tm)
#pragma unroll
                for (int tn = 0; tn < 8; ++tn)
                    mma_s8(&acc[(tm * 8 + tn) * 4], afr[tm], bfr[tn]);
        }
        __syncthreads();
    }

    // ---- epilogue: zero-point corrections + scale ----
    const int gq = lane >> 2;        // groupID
    const int tig = lane & 3;
#pragma unroll
    for (int tm = 0; tm < 2; ++tm) {
        int m_top = m0 + wm * 32 + tm * 16 + gq;
        int rs0 = CONST_TERM - 32 * g_rowsumA[m_top];
        int rs1 = CONST_TERM - 32 * g_rowsumA[m_top + 8];
        float* row0 = out + (size_t)m_top * NDIM;
        float* row1 = out + (size_t)(m_top + 8) * NDIM;
#pragma unroll
        for (int tn = 0; tn < 8; ++tn) {
            int n = n0 + wn * 64 + tn * 8 + tig * 2;
            int cs0 = 66 * g_colsumB[n];
            int cs1 = 66 * g_colsumB[n + 1];
            const int* c = &acc[(tm * 8 + tn) * 4];
            float2 v0, v1;
            v0.x = (float)(c[0] + rs0 + cs0) * OUT_SCALE;
            v0.y = (float)(c[1] + rs0 + cs1) * OUT_SCALE;
            v1.x = (float)(c[2] + rs1 + cs0) * OUT_SCALE;
            v1.y = (float)(c[3] + rs1 + cs1) * OUT_SCALE;
            *(float2*)(row0 + n) = v0;
            *(float2*)(row1 + n) = v1;
        }
    }
}

// ============================================================================
// Host
// ============================================================================
extern "C" void kernel_launch(void* const* d_in, const int* in_sizes, int n_in,
                              void* d_out, int out_size) {
    const int* x = (const int*)d_in[0];   // [M,K] int32
    const int* y = (const int*)d_in[1];   // [K,N] int32
    float* out = (float*)d_out;

    void *pxa = nullptr, *pyb = nullptr, *prs = nullptr, *pcs = nullptr;
    cudaGetSymbolAddress(&pxa, g_xa4);
    cudaGetSymbolAddress(&pyb, g_yb4);
    cudaGetSymbolAddress(&prs, g_rowsumA);
    cudaGetSymbolAddress(&pcs, g_colsumB);

    // 1) int32 -> s8 conversions (y transposed, -128 shift)
    int n16 = MDIM * KDIM / 16;
    convert_x_kernel<<<(n16 + 255) / 256, 256>>>((const int4*)x, (int4*)pxa, n16);
    convert_yT_kernel<<<dim3(NDIM / 64, KDIM / 64), 256>>>(y, (char*)pyb);

    // 2) zero-point correction sums
    rowsum_kernel<<<MDIM, 256>>>((const int*)pxa, (int*)prs);
    rowsum_kernel<<<NDIM, 256>>>((const int*)pyb, (int*)pcs);

    // 3) GEMM
    static bool attr_set = false;
    if (!attr_set) {
        cudaFuncSetAttribute(gemm_kernel,
                             cudaFuncAttributeMaxDynamicSharedMemorySize,
                             SMEM_TOTAL);
        attr_set = true;
    }
    gemm_kernel<<<GRID_M * GRID_N, 256, SMEM_TOTAL>>>(out);
}

// round 5
// speedup vs baseline: 1.0202x; 1.0202x over previous
#include <cuda_runtime.h>
#include <cuda.h>
#include <cstdint>
#include <cstddef>

// ============================================================================
// out[M,N] = ((x + 66)*0.03) @ ((y - 160)*0.025),  x s8-range, y u8-range
// Integer reformulation:  a = x (s8),  b = y - 128 (s8)
//   (x+66)(y-160) = (a+66)(b-32) = ab - 32 a + 66 b - 2112
//   out = 7.5e-4 * ( A@B - 32*rowsumA[m] + 66*colsumB[n] - 2112*K )
// Engine: mma.sync.aligned.m16n8k32.s8 (harness compiles for plain sm_103,
// so tcgen05/sm_103a instructions are unavailable).
// R5: 512 threads / 16 warps (4 warps/SMSP), warp tile 32x32, one
// __syncthreads per mainloop iter -> attack latency-boundedness.
// ============================================================================

static constexpr int MDIM = 4096, NDIM = 4096, KDIM = 4096;

static constexpr int TM = 128;        // CTA M tile
static constexpr int TN = 128;        // CTA N tile
static constexpr int TKB = 128;       // K bytes (= k elems, s8) per stage
static constexpr int NK = KDIM / TKB; // 32 mainloop iters
static constexpr int STAGES = 4;
static constexpr int A_STG = TM * TKB;              // 16 KB
static constexpr int B_STG = TN * TKB;              // 16 KB
static constexpr int STAGE_BYTES = A_STG + B_STG;   // 32 KB
static constexpr int SMEM_TOTAL = STAGES * STAGE_BYTES;  // 128 KB

static constexpr int GRID_M = MDIM / TM;  // 32
static constexpr int GRID_N = NDIM / TN;  // 32

static constexpr float OUT_SCALE = 0.03f * 0.025f;        // 7.5e-4
static constexpr int CONST_TERM = -2112 * KDIM;           // -8650752

// Scratch (device globals: no runtime allocation allowed). int4 for alignment.
__device__ int4 g_xa4[(size_t)MDIM * KDIM / 16];   // A  s8 [M,K] (x)
__device__ int4 g_yb4[(size_t)NDIM * KDIM / 16];   // Bt s8 [N,K] (y-128, transposed)
__device__ int  g_rowsumA[MDIM];
__device__ int  g_colsumB[NDIM];

#define DEVINL __device__ __forceinline__

DEVINL uint32_t smem_u32(const void* p) {
    uint32_t a;
    asm("{ .reg .u64 t; cvta.to.shared.u64 t, %1; cvt.u32.u64 %0, t; }"
        : "=r"(a) : "l"(p));
    return a;
}

DEVINL void cp_async16(uint32_t dst, const void* src) {
    asm volatile("cp.async.cg.shared.global [%0], [%1], 16;"
                 :: "r"(dst), "l"(src) : "memory");
}
DEVINL void cp_commit() { asm volatile("cp.async.commit_group;" ::: "memory"); }
template <int N>
DEVINL void cp_wait() { asm volatile("cp.async.wait_group %0;" :: "n"(N) : "memory"); }

DEVINL void ldsm4(uint32_t* r, uint32_t addr) {
    asm volatile("ldmatrix.sync.aligned.m8n8.x4.shared.b16 {%0,%1,%2,%3}, [%4];"
                 : "=r"(r[0]), "=r"(r[1]), "=r"(r[2]), "=r"(r[3]) : "r"(addr));
}

DEVINL void mma_s8(int* c, const uint32_t* a, const uint32_t* b) {
    asm volatile(
        "mma.sync.aligned.m16n8k32.row.col.s32.s8.s8.s32 "
        "{%0,%1,%2,%3}, {%4,%5,%6,%7}, {%8,%9}, {%0,%1,%2,%3};"
        : "+r"(c[0]), "+r"(c[1]), "+r"(c[2]), "+r"(c[3])
        : "r"(a[0]), "r"(a[1]), "r"(a[2]), "r"(a[3]), "r"(b[0]), "r"(b[1]));
}

// ============================================================================
// Conversion kernels
// ============================================================================

// x int32 [M,K] -> s8 [M,K]. Thread: 16 ints -> 16 bytes.
__global__ void convert_x_kernel(const int4* __restrict__ in,
                                 int4* __restrict__ out, int n16) {
    int i = blockIdx.x * blockDim.x + threadIdx.x;
    if (i >= n16) return;
    uint32_t w[4];
#pragma unroll
    for (int j = 0; j < 4; ++j) {
        int4 v = in[i * 4 + j];
        w[j] = (uint32_t)(v.x & 255) | ((uint32_t)(v.y & 255) << 8) |
               ((uint32_t)(v.z & 255) << 16) | ((uint32_t)v.w << 24);
    }
    out[i] = make_int4((int)w[0], (int)w[1], (int)w[2], (int)w[3]);
}

// y int32 [K,N] -> s8 Bt [N,K] with (y - 128). 64x64 tiles via smem.
__global__ void convert_yT_kernel(const int* __restrict__ y,
                                  char* __restrict__ bt) {
    __shared__ char tile[64][80];    // [n][k], padded row 80B (16B-aligned)
    int k0 = blockIdx.y * 64;
    int n0 = blockIdx.x * 64;
    int tid = threadIdx.x;           // 256 threads

#pragma unroll
    for (int q = 0; q < 16; ++q) {
        int idx = q * 256 + tid;
        int kk = idx >> 6;
        int nn = idx & 63;
        int v = y[(size_t)(k0 + kk) * NDIM + n0 + nn] - 128;
        tile[nn][kk] = (char)v;
    }
    __syncthreads();
    {
        int row = tid >> 2;          // n 0..63
        int c = tid & 3;             // 16B chunk 0..3
        uint4 v = *(const uint4*)&tile[row][c * 16];
        *(uint4*)&bt[(size_t)(n0 + row) * KDIM + k0 + c * 16] = v;
    }
}

// Per-row signed-byte sum of a [4096 x 4096] s8 matrix. Block = one row.
__global__ void rowsum_kernel(const int* __restrict__ m, int* __restrict__ sums) {
    __shared__ int red[256];
    const int* row = m + (size_t)blockIdx.x * (KDIM / 4);
    int acc = 0;
#pragma unroll 4
    for (int i = threadIdx.x; i < KDIM / 4; i += 256)
        acc = __dp4a(row[i], 0x01010101, acc);
    red[threadIdx.x] = acc;
    __syncthreads();
    for (int s = 128; s > 0; s >>= 1) {
        if (threadIdx.x < s) red[threadIdx.x] += red[threadIdx.x + s];
        __syncthreads();
    }
    if (threadIdx.x == 0) sums[blockIdx.x] = red[0];
}

// ============================================================================
// GEMM: 128x128 CTA tile, 16 warps (4m x 4n), warp tile 32x32,
// mma.m16n8k32.s8, 4-deep cp.async pipeline, XOR-swizzled smem,
// ONE __syncthreads per mainloop iteration.
// ============================================================================
__global__ void __launch_bounds__(512, 1)
gemm_kernel(float* __restrict__ out) {
    extern __shared__ __align__(1024) char smem[];
    const uint32_t sb = smem_u32(smem);
    const char* A = (const char*)g_xa4;
    const char* B = (const char*)g_yb4;

    const int tid = threadIdx.x;
    const int lane = tid & 31;
    const int wid = tid >> 5;      // 0..15
    const int wm = wid & 3;        // 0..3 (m)
    const int wn = wid >> 2;       // 0..3 (n)

    // Rasterization: groups of 8 m-tiles, n fast within group.
    int pid = blockIdx.x;
    int g = pid >> 8;                  // / (8*GRID_N)
    int r = pid & 255;
    int m0 = (g * 8 + (r & 7)) * TM;
    int n0 = (r >> 3) * TN;

    // ldmatrix lane geometry (fragment layouts of m16n8k32.s8)
    const int a_row16 = ((lane >> 3) & 1) * 8 + (lane & 7);  // row within m16
    const int a_kh = lane >> 4;                              // 16B half of k32
    const int b_row16 = ((lane >> 4) & 1) * 8 + (lane & 7);  // row within n16
    const int b_kh = (lane >> 3) & 1;

    const int rowA0 = wm * 32 + a_row16;        // + tm*16
    const int rowB0 = wn * 32 + b_row16;        // + gg*16

    int acc[32];
#pragma unroll
    for (int i = 0; i < 32; ++i) acc[i] = 0;

    // ---- cp.async stage copy (512 threads: 2 A chunks + 2 B chunks each) ----
    auto stage_copy = [&](int slot, int kt) {
        uint32_t abase = sb + slot * STAGE_BYTES;
        uint32_t bbase = abase + A_STG;
#pragma unroll
        for (int i = 0; i < 2; ++i) {
            int idx = tid + i * 512;
            int row = idx >> 3, c = idx & 7;
            cp_async16(abase + row * 128 + ((c ^ (row & 7)) << 4),
                       A + (size_t)(m0 + row) * KDIM + kt * TKB + c * 16);
        }
#pragma unroll
        for (int i = 0; i < 2; ++i) {
            int idx = tid + i * 512;
            int row = idx >> 3, c = idx & 7;
            cp_async16(bbase + row * 128 + ((c ^ (row & 7)) << 4),
                       B + (size_t)(n0 + row) * KDIM + kt * TKB + c * 16);
        }
    };

    // ---- prologue: stages 0..2 in flight ----
#pragma unroll
    for (int s = 0; s < STAGES - 1; ++s) {
        stage_copy(s, s);
        cp_commit();
    }
    cp_wait<STAGES - 2>();   // stage 0 resident
    __syncthreads();

    // ---- mainloop: copy stage kt+3, compute stage kt, wait stage kt+1 ----
    for (int kt = 0; kt < NK; ++kt) {
        int pf = kt + STAGES - 1;
        if (pf < NK) stage_copy(pf & 3, pf);
        cp_commit();

        uint32_t abase = sb + (kt & 3) * STAGE_BYTES;
        uint32_t bbase = abase + A_STG;

#pragma unroll
        for (int ks = 0; ks < 4; ++ks) {
            uint32_t afr[2][4];
#pragma unroll
            for (int tm = 0; tm < 2; ++tm) {
                int rowa = rowA0 + tm * 16;
                ldsm4(afr[tm],
                      abase + rowa * 128 + (((ks * 2 + a_kh) ^ (rowa & 7)) << 4));
            }
            uint32_t bfr[4][2];
#pragma unroll
            for (int gg = 0; gg < 2; ++gg) {
                uint32_t t4[4];
                int rowb = rowB0 + gg * 16;
                ldsm4(t4,
                      bbase + rowb * 128 + (((ks * 2 + b_kh) ^ (rowb & 7)) << 4));
                bfr[2 * gg][0] = t4[0]; bfr[2 * gg][1] = t4[1];
                bfr[2 * gg + 1][0] = t4[2]; bfr[2 * gg + 1][1] = t4[3];
            }
#pragma unroll
            for (int tm = 0; tm < 2; ++tm)
#pragma unroll
                for (int tn = 0; tn < 4; ++tn)
                    mma_s8(&acc[(tm * 4 + tn) * 4], afr[tm], bfr[tn]);
        }

        // stage kt+1 must be resident before next iter; barrier also orders
        // this iter's reads of slot kt&3 before iter kt+1's copy into
        // slot (kt+4)&3 == (kt)&3 ... (distinct until reuse, which the
        // barrier chain protects).
        cp_wait<STAGES - 2>();
        __syncthreads();
    }

    // ---- epilogue: zero-point corrections + scale ----
    const int gq = lane >> 2;        // groupID (row within 8)
    const int tig = lane & 3;        // thread-in-group (col pair)
#pragma unroll
    for (int tm = 0; tm < 2; ++tm) {
        int m_top = m0 + wm * 32 + tm * 16 + gq;
        int rs0 = CONST_TERM - 32 * g_rowsumA[m_top];
        int rs1 = CONST_TERM - 32 * g_rowsumA[m_top + 8];
        float* row0 = out + (size_t)m_top * NDIM;
        float* row1 = out + (size_t)(m_top + 8) * NDIM;
#pragma unroll
        for (int tn = 0; tn < 4; ++tn) {
            int n = n0 + wn * 32 + tn * 8 + tig * 2;
            int cs0 = 66 * g_colsumB[n];
            int cs1 = 66 * g_colsumB[n + 1];
            const int* c = &acc[(tm * 4 + tn) * 4];
            float2 v0, v1;
            v0.x = (float)(c[0] + rs0 + cs0) * OUT_SCALE;
            v0.y = (float)(c[1] + rs0 + cs1) * OUT_SCALE;
            v1.x = (float)(c[2] + rs1 + cs0) * OUT_SCALE;
            v1.y = (float)(c[3] + rs1 + cs1) * OUT_SCALE;
            *(float2*)(row0 + n) = v0;
            *(float2*)(row1 + n) = v1;
        }
    }
}

// ============================================================================
// Host
// ============================================================================
extern "C" void kernel_launch(void* const* d_in, const int* in_sizes, int n_in,
                              void* d_out, int out_size) {
    const int* x = (const int*)d_in[0];   // [M,K] int32
    const int* y = (const int*)d_in[1];   // [K,N] int32
    float* out = (float*)d_out;

    void *pxa = nullptr, *pyb = nullptr, *prs = nullptr, *pcs = nullptr;
    cudaGetSymbolAddress(&pxa, g_xa4);
    cudaGetSymbolAddress(&pyb, g_yb4);
    cudaGetSymbolAddress(&prs, g_rowsumA);
    cudaGetSymbolAddress(&pcs, g_colsumB);

    // 1) int32 -> s8 conversions (y transposed, -128 shift)
    int n16 = MDIM * KDIM / 16;
    convert_x_kernel<<<(n16 + 255) / 256, 256>>>((const int4*)x, (int4*)pxa, n16);
    convert_yT_kernel<<<dim3(NDIM / 64, KDIM / 64), 256>>>(y, (char*)pyb);

    // 2) zero-point correction sums
    rowsum_kernel<<<MDIM, 256>>>((const int*)pxa, (int*)prs);
    rowsum_kernel<<<NDIM, 256>>>((const int*)pyb, (int*)pcs);

    // 3) GEMM
    static bool attr_set = false;
    if (!attr_set) {
        cudaFuncSetAttribute(gemm_kernel,
                             cudaFuncAttributeMaxDynamicSharedMemorySize,
                             SMEM_TOTAL);
        attr_set = true;
    }
    gemm_kernel<<<GRID_M * GRID_N, 512, SMEM_TOTAL>>>(out);
}

// round 6
// speedup vs baseline: 2.2895x; 2.2441x over previous
#include <cuda_runtime.h>
#include <cuda.h>
#include <cuda_bf16.h>
#include <cstdint>
#include <cstddef>

// ============================================================================
// out[M,N] = ((x + 66)*0.03) @ ((y - 160)*0.025)
// (x+66) and (y-160) are exact integers in bf16 (|v| <= 256) -> convert once,
// run bf16 HMMA GEMM (mma.sync.m16n8k16, plain sm_103-legal) with fp32 acc,
// scale by 0.03*0.025 in the epilogue. No zero-point correction needed.
// R6: testing whether legacy bf16 HMMA beats the ~270 MAC/cyc/SM fallback-IMMA
// ceiling measured in R4/R5.
// ============================================================================

static constexpr int MDIM = 4096, NDIM = 4096, KDIM = 4096;

static constexpr int TM = 128;        // CTA M tile
static constexpr int TN = 128;        // CTA N tile
static constexpr int TKE = 64;        // K elems (bf16) per stage = 128 B rows
static constexpr int NK = KDIM / TKE; // 64 mainloop iters
static constexpr int STAGES = 4;
static constexpr int A_STG = TM * 128;              // 16 KB
static constexpr int B_STG = TN * 128;              // 16 KB
static constexpr int STAGE_BYTES = A_STG + B_STG;   // 32 KB
static constexpr int SMEM_TOTAL = STAGES * STAGE_BYTES;  // 128 KB

static constexpr int GRID_M = MDIM / TM;  // 32
static constexpr int GRID_N = NDIM / TN;  // 32

static constexpr float OUT_SCALE = 0.03f * 0.025f;   // 7.5e-4

// Scratch operands (device globals: no runtime allocation allowed)
__device__ __nv_bfloat16 g_xb[(size_t)MDIM * KDIM];   // A [M,K]: bf16(x+66)
__device__ __nv_bfloat16 g_yb[(size_t)NDIM * KDIM];   // Bt [N,K]: bf16(y-160)

#define DEVINL __device__ __forceinline__

DEVINL uint32_t smem_u32(const void* p) {
    uint32_t a;
    asm("{ .reg .u64 t; cvta.to.shared.u64 t, %1; cvt.u32.u64 %0, t; }"
        : "=r"(a) : "l"(p));
    return a;
}

DEVINL void cp_async16(uint32_t dst, const void* src) {
    asm volatile("cp.async.cg.shared.global [%0], [%1], 16;"
                 :: "r"(dst), "l"(src) : "memory");
}
DEVINL void cp_commit() { asm volatile("cp.async.commit_group;" ::: "memory"); }
template <int N>
DEVINL void cp_wait() { asm volatile("cp.async.wait_group %0;" :: "n"(N) : "memory"); }

DEVINL void ldsm4(uint32_t* r, uint32_t addr) {
    asm volatile("ldmatrix.sync.aligned.m8n8.x4.shared.b16 {%0,%1,%2,%3}, [%4];"
                 : "=r"(r[0]), "=r"(r[1]), "=r"(r[2]), "=r"(r[3]) : "r"(addr));
}

// m16n8k16 bf16 HMMA, f32 accumulate
DEVINL void mma_bf16(float* c, const uint32_t* a, const uint32_t* b) {
    asm volatile(
        "mma.sync.aligned.m16n8k16.row.col.f32.bf16.bf16.f32 "
        "{%0,%1,%2,%3}, {%4,%5,%6,%7}, {%8,%9}, {%0,%1,%2,%3};"
        : "+f"(c[0]), "+f"(c[1]), "+f"(c[2]), "+f"(c[3])
        : "r"(a[0]), "r"(a[1]), "r"(a[2]), "r"(a[3]), "r"(b[0]), "r"(b[1]));
}

// ============================================================================
// Conversion kernels (exact: all shifted values are integers with |v| <= 256)
// ============================================================================

// x int32 [M,K] -> bf16 (x+66), same layout.
__global__ void convert_x_kernel(const int4* __restrict__ in,
                                 __nv_bfloat162* __restrict__ out, int n4) {
    int i = blockIdx.x * blockDim.x + threadIdx.x;
    if (i >= n4) return;
    int4 v = in[i];
    out[2 * i]     = __floats2bfloat162_rn((float)(v.x + 66), (float)(v.y + 66));
    out[2 * i + 1] = __floats2bfloat162_rn((float)(v.z + 66), (float)(v.w + 66));
}

// y int32 [K,N] -> bf16 yT [N,K] with (y-160). 64(K) x 32(N) tiles.
__global__ void convert_yT_kernel(const int* __restrict__ y,
                                  __nv_bfloat16* __restrict__ yT) {
    __shared__ __nv_bfloat16 tile[64][33];   // [k][n], padded
    int k0 = blockIdx.y * 64;
    int n0 = blockIdx.x * 32;
    int tx = threadIdx.x;   // 0..31
    int ty = threadIdx.y;   // 0..7

#pragma unroll
    for (int kk = ty; kk < 64; kk += 8) {
        int vv = y[(size_t)(k0 + kk) * NDIM + n0 + tx] - 160;
        tile[kk][tx] = __float2bfloat16_rn((float)vv);
    }
    __syncthreads();
#pragma unroll
    for (int nn = ty; nn < 32; nn += 8) {
        __nv_bfloat162 p;
        p.x = tile[2 * tx + 0][nn];
        p.y = tile[2 * tx + 1][nn];
        *(__nv_bfloat162*)(&yT[(size_t)(n0 + nn) * KDIM + k0 + 2 * tx]) = p;
    }
}

// ============================================================================
// GEMM: 128x128 CTA tile, 16 warps (4m x 4n), warp tile 32x32,
// mma.m16n8k16.bf16, 4-stage cp.async pipeline, XOR-swizzled smem (128B rows).
// ============================================================================
__global__ void __launch_bounds__(512, 1)
gemm_kernel(float* __restrict__ out) {
    extern __shared__ __align__(1024) char smem[];
    const uint32_t sb = smem_u32(smem);
    const char* A = (const char*)g_xb;
    const char* B = (const char*)g_yb;

    const int tid = threadIdx.x;
    const int lane = tid & 31;
    const int wid = tid >> 5;      // 0..15
    const int wm = wid & 3;        // 0..3 (m)
    const int wn = wid >> 2;       // 0..3 (n)

    // Rasterization: groups of 8 m-tiles, n fast within group.
    int pid = blockIdx.x;
    int g = pid >> 8;                  // / (8*GRID_N)
    int r = pid & 255;
    int m0 = (g * 8 + (r & 7)) * TM;
    int n0 = (r >> 3) * TN;

    // ldmatrix lane geometry for m16n8k16 bf16 (A and B use the same map):
    // row-within-16 = ((lane>>3)&1)*8 + (lane&7), 16B-half of k16 = lane>>4
    const int frag_row = ((lane >> 3) & 1) * 8 + (lane & 7);
    const int frag_kh = lane >> 4;

    const int rowA0 = wm * 32 + frag_row;        // + tm*16
    const int rowB0 = wn * 32 + frag_row;        // + gg*16

    float acc[32];
#pragma unroll
    for (int i = 0; i < 32; ++i) acc[i] = 0.0f;

    // ---- cp.async stage copy (512 threads: 2 A chunks + 2 B chunks each) ----
    // gmem row = 4096 bf16 = 8192 B; stage covers 128 B (64 k-elems).
    auto stage_copy = [&](int slot, int kt) {
        uint32_t abase = sb + slot * STAGE_BYTES;
        uint32_t bbase = abase + A_STG;
#pragma unroll
        for (int i = 0; i < 2; ++i) {
            int idx = tid + i * 512;
            int row = idx >> 3, c = idx & 7;
            cp_async16(abase + row * 128 + ((c ^ (row & 7)) << 4),
                       A + (size_t)(m0 + row) * (KDIM * 2) + kt * 128 + c * 16);
        }
#pragma unroll
        for (int i = 0; i < 2; ++i) {
            int idx = tid + i * 512;
            int row = idx >> 3, c = idx & 7;
            cp_async16(bbase + row * 128 + ((c ^ (row & 7)) << 4),
                       B + (size_t)(n0 + row) * (KDIM * 2) + kt * 128 + c * 16);
        }
    };

    // ---- prologue: stages 0..2 in flight ----
#pragma unroll
    for (int s = 0; s < STAGES - 1; ++s) {
        stage_copy(s, s);
        cp_commit();
    }
    cp_wait<STAGES - 2>();   // stage 0 resident
    __syncthreads();

    // ---- mainloop ----
    for (int kt = 0; kt < NK; ++kt) {
        int pf = kt + STAGES - 1;
        if (pf < NK) stage_copy(pf & 3, pf);
        cp_commit();

        uint32_t abase = sb + (kt & 3) * STAGE_BYTES;
        uint32_t bbase = abase + A_STG;

#pragma unroll
        for (int ks = 0; ks < 4; ++ks) {        // 4 x k16 per stage
            uint32_t afr[2][4];
#pragma unroll
            for (int tm = 0; tm < 2; ++tm) {
                int rowa = rowA0 + tm * 16;
                ldsm4(afr[tm],
                      abase + rowa * 128 + (((ks * 2 + frag_kh) ^ (rowa & 7)) << 4));
            }
            uint32_t bfr[4][2];
#pragma unroll
            for (int gg = 0; gg < 2; ++gg) {    // n16 per ldsm.x4
                uint32_t t4[4];
                int rowb = rowB0 + gg * 16;
                ldsm4(t4,
                      bbase + rowb * 128 + (((ks * 2 + frag_kh) ^ (rowb & 7)) << 4));
                // t0=[n0-7,k0-7] t1=[n8-15,k0-7] t2=[n0-7,k8-15] t3=[n8-15,k8-15]
                bfr[2 * gg][0] = t4[0]; bfr[2 * gg][1] = t4[2];
                bfr[2 * gg + 1][0] = t4[1]; bfr[2 * gg + 1][1] = t4[3];
            }
#pragma unroll
            for (int tm = 0; tm < 2; ++tm)
#pragma unroll
                for (int tn = 0; tn < 4; ++tn)
                    mma_bf16(&acc[(tm * 4 + tn) * 4], afr[tm], bfr[tn]);
        }

        cp_wait<STAGES - 2>();
        __syncthreads();
    }

    // ---- epilogue: scale + store ----
    const int gq = lane >> 2;        // row within 8
    const int tig = lane & 3;        // col pair
#pragma unroll
    for (int tm = 0; tm < 2; ++tm) {
        int m_top = m0 + wm * 32 + tm * 16 + gq;
        float* row0 = out + (size_t)m_top * NDIM;
        float* row1 = out + (size_t)(m_top + 8) * NDIM;
#pragma unroll
        for (int tn = 0; tn < 4; ++tn) {
            int n = n0 + wn * 32 + tn * 8 + tig * 2;
            const float* c = &acc[(tm * 4 + tn) * 4];
            float2 v0, v1;
            v0.x = c[0] * OUT_SCALE;
            v0.y = c[1] * OUT_SCALE;
            v1.x = c[2] * OUT_SCALE;
            v1.y = c[3] * OUT_SCALE;
            *(float2*)(row0 + n) = v0;
            *(float2*)(row1 + n) = v1;
        }
    }
}

// ============================================================================
// Host
// ============================================================================
extern "C" void kernel_launch(void* const* d_in, const int* in_sizes, int n_in,
                              void* d_out, int out_size) {
    const int* x = (const int*)d_in[0];   // [M,K] int32
    const int* y = (const int*)d_in[1];   // [K,N] int32
    float* out = (float*)d_out;

    void *pxb = nullptr, *pyb = nullptr;
    cudaGetSymbolAddress(&pxb, g_xb);
    cudaGetSymbolAddress(&pyb, g_yb);

    // 1) int32 -> bf16 conversions (shifts folded in; y transposed)
    int n4 = MDIM * KDIM / 4;
    convert_x_kernel<<<(n4 + 255) / 256, 256>>>((const int4*)x,
                                                (__nv_bfloat162*)pxb, n4);
    convert_yT_kernel<<<dim3(NDIM / 32, KDIM / 64), dim3(32, 8)>>>(
        y, (__nv_bfloat16*)pyb);

    // 2) GEMM
    static bool attr_set = false;
    if (!attr_set) {
        cudaFuncSetAttribute(gemm_kernel,
                             cudaFuncAttributeMaxDynamicSharedMemorySize,
                             SMEM_TOTAL);
        attr_set = true;
    }
    gemm_kernel<<<GRID_M * GRID_N, 512, SMEM_TOTAL>>>(out);
}